// round 4
// baseline (speedup 1.0000x reference)
#include <cuda_runtime.h>
#include <math.h>

#define Bn 2
#define Ln 1024
#define Dn 1024
#define Hn 16
#define HDn 64
#define NT 2048       // Bn*Ln tokens
#define NCn 16        // chunks per sequence (Ln/64)
#define BHn 32        // Bn*Hn

// ---------------- scratch (static device globals; no allocation allowed) ---
__device__ float g_q[NT * Dn];
__device__ float g_k[NT * Dn];
__device__ float g_v[NT * Dn];
__device__ float g_attn[NT * Dn];
__device__ float g_beta[NT * Hn];
__device__ float g_sdelta[BHn * NCn * HDn * HDn];
__device__ float g_sprefix[BHn * NCn * HDn * HDn];

// ---------------- SGEMM: 128x128 tile, BK=8, 256 threads, 8x8/thread -------
__device__ __forceinline__ void sgemm_body(const float* __restrict__ A,
                                           const float* __restrict__ B,
                                           float* __restrict__ C,
                                           int K, int N) {
    __shared__ float As[8 * 132];
    __shared__ float Bs[8 * 132];
    const int tid = threadIdx.x;
    const int tx = tid & 15, ty = tid >> 4;
    const int row0 = blockIdx.y * 128, col0 = blockIdx.x * 128;
    const int arow = tid >> 1, acol = (tid & 1) * 4;
    const int brow = tid >> 5, bcol = (tid & 31) * 4;

    float acc[8][8];
#pragma unroll
    for (int i = 0; i < 8; i++)
#pragma unroll
        for (int j = 0; j < 8; j++) acc[i][j] = 0.f;

    const float* Ap = A + (size_t)(row0 + arow) * K + acol;
    const float* Bp = B + (size_t)brow * N + col0 + bcol;

    for (int k0 = 0; k0 < K; k0 += 8) {
        float4 av = *(const float4*)Ap; Ap += 8;
        float4 bv = *(const float4*)Bp; Bp += (size_t)8 * N;
        As[(acol + 0) * 132 + arow] = av.x;
        As[(acol + 1) * 132 + arow] = av.y;
        As[(acol + 2) * 132 + arow] = av.z;
        As[(acol + 3) * 132 + arow] = av.w;
        *(float4*)&Bs[brow * 132 + bcol] = bv;
        __syncthreads();
#pragma unroll
        for (int kk = 0; kk < 8; kk++) {
            float a[8], b[8];
            *(float4*)&a[0] = *(const float4*)&As[kk * 132 + ty * 8];
            *(float4*)&a[4] = *(const float4*)&As[kk * 132 + ty * 8 + 4];
            *(float4*)&b[0] = *(const float4*)&Bs[kk * 132 + tx * 8];
            *(float4*)&b[4] = *(const float4*)&Bs[kk * 132 + tx * 8 + 4];
#pragma unroll
            for (int i = 0; i < 8; i++)
#pragma unroll
                for (int j = 0; j < 8; j++) acc[i][j] += a[i] * b[j];
        }
        __syncthreads();
    }
#pragma unroll
    for (int i = 0; i < 8; i++) {
        float* Cp = C + (size_t)(row0 + ty * 8 + i) * N + col0 + tx * 8;
        *(float4*)Cp       = make_float4(acc[i][0], acc[i][1], acc[i][2], acc[i][3]);
        *(float4*)(Cp + 4) = make_float4(acc[i][4], acc[i][5], acc[i][6], acc[i][7]);
    }
}

__global__ void __launch_bounds__(256) sgemm_qkv_kernel(
    const float* __restrict__ x, const float* __restrict__ Wq,
    const float* __restrict__ Wk, const float* __restrict__ Wv) {
    const float* Bm = (blockIdx.z == 0) ? Wq : (blockIdx.z == 1) ? Wk : Wv;
    float* Cm = (blockIdx.z == 0) ? g_q : (blockIdx.z == 1) ? g_k : g_v;
    sgemm_body(x, Bm, Cm, Dn, Dn);
}

__global__ void __launch_bounds__(256) sgemm_out_kernel(
    const float* __restrict__ Wo, float* __restrict__ C) {
    sgemm_body(g_attn, Wo, C, Dn, Dn);
}

// ---------------- beta = sigmoid(x @ Wb + bb) ------------------------------
__global__ void __launch_bounds__(256) beta_kernel(const float* __restrict__ x,
                                                   const float* __restrict__ Wb,
                                                   const float* __restrict__ bbias) {
    __shared__ float sx[16 * 64];
    __shared__ float sW[64 * 16];
    const int tid = threadIdx.x;
    const int tx = tid & 15, ty = tid >> 4;
    const int row0 = blockIdx.x * 16;
    float acc = 0.f;
    for (int k0 = 0; k0 < Dn; k0 += 64) {
        {
            int r = tid >> 4, c4 = (tid & 15) * 4;
            *(float4*)&sx[r * 64 + c4] =
                *(const float4*)&x[(size_t)(row0 + r) * Dn + k0 + c4];
            int wr = tid >> 2, wc4 = (tid & 3) * 4;
            *(float4*)&sW[wr * 16 + wc4] =
                *(const float4*)&Wb[(size_t)(k0 + wr) * Hn + wc4];
        }
        __syncthreads();
#pragma unroll
        for (int kk = 0; kk < 64; kk++)
            acc += sx[ty * 64 + kk] * sW[kk * 16 + tx];
        __syncthreads();
    }
    acc += bbias[tx];
    g_beta[(size_t)(row0 + ty) * Hn + tx] = 1.f / (1.f + expf(-acc));
}

// ---------------- L2 normalize q,k per (b,l,h) over HD=64 ------------------
__global__ void __launch_bounds__(256) l2norm_kernel() {
    int gw = (blockIdx.x * 256 + threadIdx.x) >> 5;   // warp id, 0..2*NT*Hn-1
    int lane = threadIdx.x & 31;
    float* ptr = (gw < NT * Hn) ? g_q : g_k;
    int row = (gw < NT * Hn) ? gw : gw - NT * Hn;
    size_t base = (size_t)(row >> 4) * Dn + (row & 15) * 64;
    float2 v = *(float2*)&ptr[base + lane * 2];
    float s = v.x * v.x + v.y * v.y;
#pragma unroll
    for (int o = 16; o > 0; o >>= 1) s += __shfl_xor_sync(0xffffffffu, s, o);
    float scale = 1.f / fmaxf(sqrtf(s), 1e-12f);
    v.x *= scale; v.y *= scale;
    *(float2*)&ptr[base + lane * 2] = v;
}

// ---------------- per-chunk state delta: dS = (beta*k)^T @ v ---------------
__global__ void __launch_bounds__(256) chunk_delta_kernel() {
    __shared__ float skb[64 * 64];
    __shared__ float sv[64 * 64];
    __shared__ float sbeta[64];
    const int c = blockIdx.x, bh = blockIdx.y;
    const int b = bh >> 4, h = bh & 15;
    const int tid = threadIdx.x;
    const int tx = tid & 15, ty = tid >> 4;
    const size_t rowbase = (size_t)b * Ln + c * 64;

    if (tid < 64) sbeta[tid] = g_beta[(rowbase + tid) * Hn + h];
    __syncthreads();
#pragma unroll
    for (int r = 0; r < 4; r++) {
        int t = r * 16 + (tid >> 4);
        int e4 = (tid & 15) * 4;
        size_t g = (rowbase + t) * Dn + h * 64 + e4;
        float4 kv = *(const float4*)&g_k[g];
        float bt = sbeta[t];
        kv.x *= bt; kv.y *= bt; kv.z *= bt; kv.w *= bt;
        *(float4*)&skb[t * 64 + e4] = kv;
        *(float4*)&sv[t * 64 + e4] = *(const float4*)&g_v[g];
    }
    __syncthreads();

    float acc[4][4];
#pragma unroll
    for (int i = 0; i < 4; i++)
#pragma unroll
        for (int j = 0; j < 4; j++) acc[i][j] = 0.f;
#pragma unroll 8
    for (int t = 0; t < 64; t++) {
        float4 a = *(const float4*)&skb[t * 64 + ty * 4];
        float4 b4 = *(const float4*)&sv[t * 64 + tx * 4];
        const float af[4] = {a.x, a.y, a.z, a.w};
        const float bf[4] = {b4.x, b4.y, b4.z, b4.w};
#pragma unroll
        for (int i = 0; i < 4; i++)
#pragma unroll
            for (int j = 0; j < 4; j++) acc[i][j] += af[i] * bf[j];
    }
    const size_t sbase = ((size_t)bh * NCn + c) * 4096;
#pragma unroll
    for (int i = 0; i < 4; i++)
        *(float4*)&g_sdelta[sbase + (ty * 4 + i) * 64 + tx * 4] =
            make_float4(acc[i][0], acc[i][1], acc[i][2], acc[i][3]);
}

// ---------------- serial prefix over 16 chunk states per (b,h) -------------
__global__ void __launch_bounds__(256) prefix_kernel() {
    const int bh = blockIdx.x;
    const int tid = threadIdx.x;
    float4 acc[4];
#pragma unroll
    for (int j = 0; j < 4; j++) acc[j] = make_float4(0.f, 0.f, 0.f, 0.f);
    for (int c = 0; c < NCn; c++) {
        size_t base = ((size_t)bh * NCn + c) * 4096;
#pragma unroll
        for (int j = 0; j < 4; j++) {
            int off = j * 1024 + tid * 4;
            *(float4*)&g_sprefix[base + off] = acc[j];
            float4 d = *(const float4*)&g_sdelta[base + off];
            acc[j].x += d.x; acc[j].y += d.y; acc[j].z += d.z; acc[j].w += d.w;
        }
    }
}

// ---------------- per-chunk output ----------------------------------------
// out = q @ S_prev + tril(q k^T) * beta @ v      (all 64x64x64 in smem)
__global__ void __launch_bounds__(256) chunk_out_kernel() {
    extern __shared__ float sm[];
    float* sqT = sm;              // [64][65] transposed q
    float* sX  = sm + 4160;       // multi-use: S_prev(64x64) -> kT(64x65) -> v(64x64)
    float* sA  = sm + 8320;       // [64][64], holds A^T[s][t]
    float* sbeta = sm + 12416;    // [64]
    const int c = blockIdx.x, bh = blockIdx.y;
    const int b = bh >> 4, h = bh & 15;
    const int tid = threadIdx.x;
    const int tx = tid & 15, ty = tid >> 4;
    const size_t rowbase = (size_t)b * Ln + c * 64;
    const size_t sbase = ((size_t)bh * NCn + c) * 4096;

    if (tid < 64) sbeta[tid] = g_beta[(rowbase + tid) * Hn + h];
    // load q transposed
#pragma unroll
    for (int r = 0; r < 4; r++) {
        int t = r * 16 + (tid >> 4);
        int d4 = (tid & 15) * 4;
        float4 qv = *(const float4*)&g_q[(rowbase + t) * Dn + h * 64 + d4];
        sqT[(d4 + 0) * 65 + t] = qv.x;
        sqT[(d4 + 1) * 65 + t] = qv.y;
        sqT[(d4 + 2) * 65 + t] = qv.z;
        sqT[(d4 + 3) * 65 + t] = qv.w;
    }
    // load S_prev (natural [d][e], stride 64)
#pragma unroll
    for (int r = 0; r < 4; r++) {
        int idx = r * 1024 + tid * 4;
        *(float4*)&sX[idx] = *(const float4*)&g_sprefix[sbase + idx];
    }
    __syncthreads();

    float acc[4][4];
#pragma unroll
    for (int i = 0; i < 4; i++)
#pragma unroll
        for (int j = 0; j < 4; j++) acc[i][j] = 0.f;

    // phase 1: acc = q @ S_prev
#pragma unroll 8
    for (int d = 0; d < 64; d++) {
        float a0 = sqT[d * 65 + ty * 4 + 0];
        float a1 = sqT[d * 65 + ty * 4 + 1];
        float a2v = sqT[d * 65 + ty * 4 + 2];
        float a3 = sqT[d * 65 + ty * 4 + 3];
        float4 bv = *(const float4*)&sX[d * 64 + tx * 4];
        acc[0][0] += a0 * bv.x; acc[0][1] += a0 * bv.y; acc[0][2] += a0 * bv.z; acc[0][3] += a0 * bv.w;
        acc[1][0] += a1 * bv.x; acc[1][1] += a1 * bv.y; acc[1][2] += a1 * bv.z; acc[1][3] += a1 * bv.w;
        acc[2][0] += a2v * bv.x; acc[2][1] += a2v * bv.y; acc[2][2] += a2v * bv.z; acc[2][3] += a2v * bv.w;
        acc[3][0] += a3 * bv.x; acc[3][1] += a3 * bv.y; acc[3][2] += a3 * bv.z; acc[3][3] += a3 * bv.w;
    }
    __syncthreads();
    // load k transposed into sX (stride 65)
#pragma unroll
    for (int r = 0; r < 4; r++) {
        int t = r * 16 + (tid >> 4);
        int d4 = (tid & 15) * 4;
        float4 kv = *(const float4*)&g_k[(rowbase + t) * Dn + h * 64 + d4];
        sX[(d4 + 0) * 65 + t] = kv.x;
        sX[(d4 + 1) * 65 + t] = kv.y;
        sX[(d4 + 2) * 65 + t] = kv.z;
        sX[(d4 + 3) * 65 + t] = kv.w;
    }
    __syncthreads();

    // phase 2: A[t][s] = (q_t . k_s);  mask s<=t, scale by beta[s]; store A^T
    float a2[4][4];
#pragma unroll
    for (int i = 0; i < 4; i++)
#pragma unroll
        for (int j = 0; j < 4; j++) a2[i][j] = 0.f;
#pragma unroll 8
    for (int d = 0; d < 64; d++) {
        float af[4], bf[4];
#pragma unroll
        for (int i = 0; i < 4; i++) af[i] = sqT[d * 65 + ty * 4 + i];
#pragma unroll
        for (int j = 0; j < 4; j++) bf[j] = sX[d * 65 + tx * 4 + j];
#pragma unroll
        for (int i = 0; i < 4; i++)
#pragma unroll
            for (int j = 0; j < 4; j++) a2[i][j] += af[i] * bf[j];
    }
#pragma unroll
    for (int j = 0; j < 4; j++) {
        int s = tx * 4 + j;
        float bscale = sbeta[s];
        float4 v4;
        v4.x = (s <= ty * 4 + 0) ? a2[0][j] * bscale : 0.f;
        v4.y = (s <= ty * 4 + 1) ? a2[1][j] * bscale : 0.f;
        v4.z = (s <= ty * 4 + 2) ? a2[2][j] * bscale : 0.f;
        v4.w = (s <= ty * 4 + 3) ? a2[3][j] * bscale : 0.f;
        *(float4*)&sA[s * 64 + ty * 4] = v4;   // A^T[s][t0..t0+3]
    }
    __syncthreads();
    // load v (natural, stride 64) into sX
#pragma unroll
    for (int r = 0; r < 4; r++) {
        int t = r * 16 + (tid >> 4);
        int e4 = (tid & 15) * 4;
        *(float4*)&sX[t * 64 + e4] =
            *(const float4*)&g_v[(rowbase + t) * Dn + h * 64 + e4];
    }
    __syncthreads();

    // phase 3: acc += A @ v
#pragma unroll 8
    for (int s = 0; s < 64; s++) {
        float4 av = *(const float4*)&sA[s * 64 + ty * 4];
        float4 bv = *(const float4*)&sX[s * 64 + tx * 4];
        const float af[4] = {av.x, av.y, av.z, av.w};
        const float bf[4] = {bv.x, bv.y, bv.z, bv.w};
#pragma unroll
        for (int i = 0; i < 4; i++)
#pragma unroll
            for (int j = 0; j < 4; j++) acc[i][j] += af[i] * bf[j];
    }
#pragma unroll
    for (int i = 0; i < 4; i++)
        *(float4*)&g_attn[(rowbase + ty * 4 + i) * Dn + h * 64 + tx * 4] =
            make_float4(acc[i][0], acc[i][1], acc[i][2], acc[i][3]);
}

// ---------------------------------------------------------------------------
extern "C" void kernel_launch(void* const* d_in, const int* in_sizes, int n_in,
                              void* d_out, int out_size) {
    const float* x  = (const float*)d_in[0];
    const float* Wq = (const float*)d_in[1];
    const float* Wk = (const float*)d_in[2];
    const float* Wv = (const float*)d_in[3];
    const float* Wo = (const float*)d_in[4];
    const float* Wb = (const float*)d_in[5];
    const float* bb = (const float*)d_in[6];
    float* out = (float*)d_out;

    // q,k,v projections: three 2048x1024x1024 GEMMs fused on gridDim.z
    sgemm_qkv_kernel<<<dim3(Dn / 128, NT / 128, 3), 256>>>(x, Wq, Wk, Wv);
    // gates
    beta_kernel<<<NT / 16, 256>>>(x, Wb, bb);
    // l2 normalize q,k (2*NT*Hn rows, 1 warp each, 8 warps/block)
    l2norm_kernel<<<(2 * NT * Hn) / 8, 256>>>();
    // chunk-local state deltas
    chunk_delta_kernel<<<dim3(NCn, BHn), 256>>>();
    // exclusive prefix over chunk states
    prefix_kernel<<<BHn, 256>>>();
    // per-chunk outputs (needs >48KB dynamic smem)
    cudaFuncSetAttribute(chunk_out_kernel,
                         cudaFuncAttributeMaxDynamicSharedMemorySize, 12480 * 4);
    chunk_out_kernel<<<dim3(NCn, BHn), 256, 12480 * 4>>>();
    // final projection
    sgemm_out_kernel<<<dim3(Dn / 128, NT / 128), 256>>>(Wo, out);
}

// round 6
// speedup vs baseline: 2.2323x; 2.2323x over previous
#include <cuda_runtime.h>
#include <cuda_bf16.h>
#include <math.h>
#include <stdint.h>

#define Bn 2
#define Ln 1024
#define Dn 1024
#define Hn 16
#define HDn 64
#define NT 2048       // Bn*Ln tokens
#define NCn 16        // chunks per sequence (Ln/64)
#define BHn 32        // Bn*Hn

// ---------------- scratch (static device globals; no allocation allowed) ---
__device__ float g_q[NT * Dn];
__device__ float g_k[NT * Dn];
__device__ float g_v[NT * Dn];
__device__ float g_beta[NT * Hn];
__device__ float g_sdelta[BHn * NCn * HDn * HDn];
__device__ float g_sprefix[BHn * NCn * HDn * HDn];
// bf16 hi/lo operands for tensor-core GEMMs
__device__ __nv_bfloat16 g_xh[NT * Dn], g_xl[NT * Dn];
__device__ __nv_bfloat16 g_wth[4 * Dn * Dn], g_wtl[4 * Dn * Dn];  // W^T [N][K], 4 mats
__device__ __nv_bfloat16 g_ah[NT * Dn], g_al[NT * Dn];            // attn hi/lo

// =================== helpers ===============================================
__device__ __forceinline__ uint32_t smem_u32(const void* p) {
    uint32_t a;
    asm("{ .reg .u64 t; cvta.to.shared.u64 t, %1; cvt.u32.u64 %0, t; }"
        : "=r"(a) : "l"(p));
    return a;
}
__device__ __forceinline__ void cp_async16(uint32_t saddr, const void* gptr) {
    asm volatile("cp.async.cg.shared.global [%0], [%1], 16;"
                 :: "r"(saddr), "l"(gptr) : "memory");
}
#define CP_COMMIT() asm volatile("cp.async.commit_group;" ::: "memory")
#define CP_WAIT0()  asm volatile("cp.async.wait_group 0;" ::: "memory")

// mma.sync m16n8k16 bf16 -> fp32 (HMMA path; plain compute_80+ PTX)
__device__ __forceinline__ void mma16816(float* c, const uint32_t* a, const uint32_t* b) {
    asm volatile(
        "mma.sync.aligned.m16n8k16.row.col.f32.bf16.bf16.f32 "
        "{%0,%1,%2,%3}, {%4,%5,%6,%7}, {%8,%9}, {%0,%1,%2,%3};"
        : "+f"(c[0]), "+f"(c[1]), "+f"(c[2]), "+f"(c[3])
        : "r"(a[0]), "r"(a[1]), "r"(a[2]), "r"(a[3]), "r"(b[0]), "r"(b[1]));
}

__device__ __forceinline__ void split_hl(float v, __nv_bfloat16& h, __nv_bfloat16& l) {
    h = __float2bfloat16(v);
    l = __float2bfloat16(v - __bfloat162float(h));
}

// ---------------- operand conversion kernels -------------------------------
__global__ void __launch_bounds__(256) convert_x_kernel(const float* __restrict__ x) {
    size_t i = ((size_t)blockIdx.x * 256 + threadIdx.x) * 4;
    float4 v = *(const float4*)(x + i);
    float f[4] = {v.x, v.y, v.z, v.w};
    __nv_bfloat16 h[4], l[4];
#pragma unroll
    for (int j = 0; j < 4; j++) split_hl(f[j], h[j], l[j]);
    __nv_bfloat162 h01, h23, l01, l23;
    h01.x = h[0]; h01.y = h[1]; h23.x = h[2]; h23.y = h[3];
    l01.x = l[0]; l01.y = l[1]; l23.x = l[2]; l23.y = l[3];
    *(__nv_bfloat162*)(g_xh + i)     = h01;
    *(__nv_bfloat162*)(g_xh + i + 2) = h23;
    *(__nv_bfloat162*)(g_xl + i)     = l01;
    *(__nv_bfloat162*)(g_xl + i + 2) = l23;
}

// transpose W[K][N] -> Wt[N][K], split hi/lo
__global__ void __launch_bounds__(256) convert_w_kernel(
    const float* __restrict__ Wq, const float* __restrict__ Wk,
    const float* __restrict__ Wv, const float* __restrict__ Wo) {
    __shared__ float t[32][33];
    const float* W = (blockIdx.z == 0) ? Wq : (blockIdx.z == 1) ? Wk
                   : (blockIdx.z == 2) ? Wv : Wo;
    int n0 = blockIdx.x * 32, k0 = blockIdx.y * 32;
    int tx = threadIdx.x, ty = threadIdx.y;  // block (32,8)
#pragma unroll
    for (int r = 0; r < 4; r++)
        t[ty + 8 * r][tx] = W[(size_t)(k0 + ty + 8 * r) * Dn + n0 + tx];
    __syncthreads();
    size_t ob = (size_t)blockIdx.z * Dn * Dn;
#pragma unroll
    for (int r = 0; r < 4; r++) {
        float v = t[tx][ty + 8 * r];
        size_t o = ob + (size_t)(n0 + ty + 8 * r) * Dn + k0 + tx;
        __nv_bfloat16 h, l;
        split_hl(v, h, l);
        g_wth[o] = h;
        g_wtl[o] = l;
    }
}

// ---------------- bf16 3-term MMA GEMM: C[2048x1024] = A @ Wt^T ------------
// 128x128 CTA tile, BK=32, 8 warps 2(M)x4(N), warp tile 64x32.
#define KPAD 40                        // bf16 elems per smem row (32 + 8 pad)
#define TILE_E (128 * KPAD)            // elems per operand tile
#define STAGE_E (4 * TILE_E)           // Ah, Al, Bh, Bl
#define MM_SMEM_B (2 * STAGE_E * 2)    // 81920 bytes

__device__ __forceinline__ void mm_issue_stage(
    uint32_t sbase, int s, int kc, int tid,
    const __nv_bfloat16* Ah, const __nv_bfloat16* Al,
    const __nv_bfloat16* Bh, const __nv_bfloat16* Bl) {
    uint32_t st = sbase + (uint32_t)s * (STAGE_E * 2);
#pragma unroll
    for (int j = 0; j < 2; j++) {
        int idx = tid + j * 256;               // 0..511
        int row = idx >> 2, seg = idx & 3;
        size_t go = (size_t)row * Dn + kc * 32 + seg * 8;
        uint32_t so = (uint32_t)(row * KPAD + seg * 8) * 2;
        cp_async16(st + so,                    Ah + go);
        cp_async16(st + TILE_E * 2 + so,       Al + go);
        cp_async16(st + 2 * TILE_E * 2 + so,   Bh + go);
        cp_async16(st + 3 * TILE_E * 2 + so,   Bl + go);
    }
    CP_COMMIT();
}

__device__ __forceinline__ void mm_gemm_body(
    const __nv_bfloat16* __restrict__ Agh, const __nv_bfloat16* __restrict__ Agl,
    const __nv_bfloat16* __restrict__ Bgh, const __nv_bfloat16* __restrict__ Bgl,
    float* __restrict__ C) {
    extern __shared__ __nv_bfloat16 sm[];
    const uint32_t sbase = smem_u32(sm);
    const int tid = threadIdx.x, lane = tid & 31, wid = tid >> 5;
    const int wm = wid & 1, wn = wid >> 1;
    const int m0 = blockIdx.y * 128, n0 = blockIdx.x * 128;

    const __nv_bfloat16* Ah = Agh + (size_t)m0 * Dn;
    const __nv_bfloat16* Al = Agl + (size_t)m0 * Dn;
    const __nv_bfloat16* Bh = Bgh + (size_t)n0 * Dn;
    const __nv_bfloat16* Bl = Bgl + (size_t)n0 * Dn;

    float c[4][4][4];
#pragma unroll
    for (int i = 0; i < 4; i++)
#pragma unroll
        for (int j = 0; j < 4; j++)
#pragma unroll
            for (int r = 0; r < 4; r++) c[i][j][r] = 0.f;

    mm_issue_stage(sbase, 0, 0, tid, Ah, Al, Bh, Bl);

    const int g4 = lane >> 2;          // 0..7
    const int cpair = (lane & 3) * 2;  // 0,2,4,6

    for (int kc = 0; kc < 32; kc++) {
        CP_WAIT0();
        __syncthreads();
        if (kc + 1 < 32)
            mm_issue_stage(sbase, (kc + 1) & 1, kc + 1, tid, Ah, Al, Bh, Bl);

        const __nv_bfloat16* st = sm + (kc & 1) * STAGE_E;
        const __nv_bfloat16* sAh = st;
        const __nv_bfloat16* sAl = st + TILE_E;
        const __nv_bfloat16* sBh = st + 2 * TILE_E;
        const __nv_bfloat16* sBl = st + 3 * TILE_E;

#pragma unroll
        for (int ks = 0; ks < 2; ks++) {
            const int k0 = ks * 16 + cpair;
            // B fragments for this k16 (kept live across mf loop)
            uint32_t bh[4][2], bl[4][2];
#pragma unroll
            for (int nf = 0; nf < 4; nf++) {
                int r = wn * 32 + nf * 8 + g4;
                bh[nf][0] = *(const uint32_t*)(sBh + r * KPAD + k0);
                bh[nf][1] = *(const uint32_t*)(sBh + r * KPAD + k0 + 8);
                bl[nf][0] = *(const uint32_t*)(sBl + r * KPAD + k0);
                bl[nf][1] = *(const uint32_t*)(sBl + r * KPAD + k0 + 8);
            }
#pragma unroll
            for (int mf = 0; mf < 4; mf++) {
                int r = wm * 64 + mf * 16 + g4;
                uint32_t ah[4], al[4];
                ah[0] = *(const uint32_t*)(sAh + r * KPAD + k0);
                ah[1] = *(const uint32_t*)(sAh + (r + 8) * KPAD + k0);
                ah[2] = *(const uint32_t*)(sAh + r * KPAD + k0 + 8);
                ah[3] = *(const uint32_t*)(sAh + (r + 8) * KPAD + k0 + 8);
                al[0] = *(const uint32_t*)(sAl + r * KPAD + k0);
                al[1] = *(const uint32_t*)(sAl + (r + 8) * KPAD + k0);
                al[2] = *(const uint32_t*)(sAl + r * KPAD + k0 + 8);
                al[3] = *(const uint32_t*)(sAl + (r + 8) * KPAD + k0 + 8);
#pragma unroll
                for (int nf = 0; nf < 4; nf++) {
                    mma16816(c[mf][nf], ah, bh[nf]);
                    mma16816(c[mf][nf], ah, bl[nf]);
                    mma16816(c[mf][nf], al, bh[nf]);
                }
            }
        }
        __syncthreads();
    }

    // epilogue: write fp32 C
#pragma unroll
    for (int mf = 0; mf < 4; mf++) {
        int r = m0 + wm * 64 + mf * 16 + g4;
#pragma unroll
        for (int nf = 0; nf < 4; nf++) {
            int cc = n0 + wn * 32 + nf * 8 + cpair;
            *(float2*)(C + (size_t)r * Dn + cc)       = make_float2(c[mf][nf][0], c[mf][nf][1]);
            *(float2*)(C + (size_t)(r + 8) * Dn + cc) = make_float2(c[mf][nf][2], c[mf][nf][3]);
        }
    }
}

__global__ void __launch_bounds__(256, 2) mm_qkv_kernel() {
    const size_t wo = (size_t)blockIdx.z * Dn * Dn;
    float* C = (blockIdx.z == 0) ? g_q : (blockIdx.z == 1) ? g_k : g_v;
    mm_gemm_body(g_xh, g_xl, g_wth + wo, g_wtl + wo, C);
}
__global__ void __launch_bounds__(256, 2) mm_out_kernel(float* __restrict__ out) {
    mm_gemm_body(g_ah, g_al, g_wth + 3ull * Dn * Dn, g_wtl + 3ull * Dn * Dn, out);
}

// ---------------- beta = sigmoid(x @ Wb + bb) ------------------------------
__global__ void __launch_bounds__(256) beta_kernel(const float* __restrict__ x,
                                                   const float* __restrict__ Wb,
                                                   const float* __restrict__ bbias) {
    __shared__ float sx[16 * 64];
    __shared__ float sW[64 * 16];
    const int tid = threadIdx.x;
    const int tx = tid & 15, ty = tid >> 4;
    const int row0 = blockIdx.x * 16;
    float acc = 0.f;
    for (int k0 = 0; k0 < Dn; k0 += 64) {
        {
            int r = tid >> 4, c4 = (tid & 15) * 4;
            *(float4*)&sx[r * 64 + c4] =
                *(const float4*)&x[(size_t)(row0 + r) * Dn + k0 + c4];
            int wr = tid >> 2, wc4 = (tid & 3) * 4;
            *(float4*)&sW[wr * 16 + wc4] =
                *(const float4*)&Wb[(size_t)(k0 + wr) * Hn + wc4];
        }
        __syncthreads();
#pragma unroll
        for (int kk = 0; kk < 64; kk++)
            acc += sx[ty * 64 + kk] * sW[kk * 16 + tx];
        __syncthreads();
    }
    acc += bbias[tx];
    g_beta[(size_t)(row0 + ty) * Hn + tx] = 1.f / (1.f + expf(-acc));
}

// ---------------- L2 normalize q,k per (b,l,h) over HD=64 ------------------
__global__ void __launch_bounds__(256) l2norm_kernel() {
    int gw = (blockIdx.x * 256 + threadIdx.x) >> 5;
    int lane = threadIdx.x & 31;
    float* ptr = (gw < NT * Hn) ? g_q : g_k;
    int row = (gw < NT * Hn) ? gw : gw - NT * Hn;
    size_t base = (size_t)(row >> 4) * Dn + (row & 15) * 64;
    float2 v = *(float2*)&ptr[base + lane * 2];
    float s = v.x * v.x + v.y * v.y;
#pragma unroll
    for (int o = 16; o > 0; o >>= 1) s += __shfl_xor_sync(0xffffffffu, s, o);
    float scale = 1.f / fmaxf(sqrtf(s), 1e-12f);
    v.x *= scale; v.y *= scale;
    *(float2*)&ptr[base + lane * 2] = v;
}

// ---------------- per-chunk state delta: dS = (beta*k)^T @ v ---------------
__global__ void __launch_bounds__(256) chunk_delta_kernel() {
    __shared__ float skb[64 * 64];
    __shared__ float sv[64 * 64];
    __shared__ float sbeta[64];
    const int c = blockIdx.x, bh = blockIdx.y;
    const int b = bh >> 4, h = bh & 15;
    const int tid = threadIdx.x;
    const int tx = tid & 15, ty = tid >> 4;
    const size_t rowbase = (size_t)b * Ln + c * 64;

    if (tid < 64) sbeta[tid] = g_beta[(rowbase + tid) * Hn + h];
    __syncthreads();
#pragma unroll
    for (int r = 0; r < 4; r++) {
        int t = r * 16 + (tid >> 4);
        int e4 = (tid & 15) * 4;
        size_t g = (rowbase + t) * Dn + h * 64 + e4;
        float4 kv = *(const float4*)&g_k[g];
        float bt = sbeta[t];
        kv.x *= bt; kv.y *= bt; kv.z *= bt; kv.w *= bt;
        *(float4*)&skb[t * 64 + e4] = kv;
        *(float4*)&sv[t * 64 + e4] = *(const float4*)&g_v[g];
    }
    __syncthreads();

    float acc[4][4];
#pragma unroll
    for (int i = 0; i < 4; i++)
#pragma unroll
        for (int j = 0; j < 4; j++) acc[i][j] = 0.f;
#pragma unroll 8
    for (int t = 0; t < 64; t++) {
        float4 a = *(const float4*)&skb[t * 64 + ty * 4];
        float4 b4 = *(const float4*)&sv[t * 64 + tx * 4];
        const float af[4] = {a.x, a.y, a.z, a.w};
        const float bf[4] = {b4.x, b4.y, b4.z, b4.w};
#pragma unroll
        for (int i = 0; i < 4; i++)
#pragma unroll
            for (int j = 0; j < 4; j++) acc[i][j] += af[i] * bf[j];
    }
    const size_t sbase = ((size_t)bh * NCn + c) * 4096;
#pragma unroll
    for (int i = 0; i < 4; i++)
        *(float4*)&g_sdelta[sbase + (ty * 4 + i) * 64 + tx * 4] =
            make_float4(acc[i][0], acc[i][1], acc[i][2], acc[i][3]);
}

// ---------------- serial prefix over 16 chunk states per (b,h) -------------
__global__ void __launch_bounds__(256) prefix_kernel() {
    const int bh = blockIdx.x;
    const int tid = threadIdx.x;
    float4 acc[4];
#pragma unroll
    for (int j = 0; j < 4; j++) acc[j] = make_float4(0.f, 0.f, 0.f, 0.f);
    for (int c = 0; c < NCn; c++) {
        size_t base = ((size_t)bh * NCn + c) * 4096;
#pragma unroll
        for (int j = 0; j < 4; j++) {
            int off = j * 1024 + tid * 4;
            *(float4*)&g_sprefix[base + off] = acc[j];
            float4 d = *(const float4*)&g_sdelta[base + off];
            acc[j].x += d.x; acc[j].y += d.y; acc[j].z += d.z; acc[j].w += d.w;
        }
    }
}

// ---------------- per-chunk output ----------------------------------------
// out = q @ S_prev + tril(q k^T) * beta @ v ; writes attn as bf16 hi/lo
__global__ void __launch_bounds__(256) chunk_out_kernel() {
    extern __shared__ float smf[];
    float* sqT = smf;             // [64][65] transposed q
    float* sX  = smf + 4160;      // multi-use
    float* sA  = smf + 8320;      // [64][64] A^T
    float* sbeta = smf + 12416;   // [64]
    const int c = blockIdx.x, bh = blockIdx.y;
    const int b = bh >> 4, h = bh & 15;
    const int tid = threadIdx.x;
    const int tx = tid & 15, ty = tid >> 4;
    const size_t rowbase = (size_t)b * Ln + c * 64;
    const size_t sbase = ((size_t)bh * NCn + c) * 4096;

    if (tid < 64) sbeta[tid] = g_beta[(rowbase + tid) * Hn + h];
#pragma unroll
    for (int r = 0; r < 4; r++) {
        int t = r * 16 + (tid >> 4);
        int d4 = (tid & 15) * 4;
        float4 qv = *(const float4*)&g_q[(rowbase + t) * Dn + h * 64 + d4];
        sqT[(d4 + 0) * 65 + t] = qv.x;
        sqT[(d4 + 1) * 65 + t] = qv.y;
        sqT[(d4 + 2) * 65 + t] = qv.z;
        sqT[(d4 + 3) * 65 + t] = qv.w;
    }
#pragma unroll
    for (int r = 0; r < 4; r++) {
        int idx = r * 1024 + tid * 4;
        *(float4*)&sX[idx] = *(const float4*)&g_sprefix[sbase + idx];
    }
    __syncthreads();

    float acc[4][4];
#pragma unroll
    for (int i = 0; i < 4; i++)
#pragma unroll
        for (int j = 0; j < 4; j++) acc[i][j] = 0.f;

#pragma unroll 8
    for (int d = 0; d < 64; d++) {
        float a0 = sqT[d * 65 + ty * 4 + 0];
        float a1 = sqT[d * 65 + ty * 4 + 1];
        float a2v = sqT[d * 65 + ty * 4 + 2];
        float a3 = sqT[d * 65 + ty * 4 + 3];
        float4 bv = *(const float4*)&sX[d * 64 + tx * 4];
        acc[0][0] += a0 * bv.x; acc[0][1] += a0 * bv.y; acc[0][2] += a0 * bv.z; acc[0][3] += a0 * bv.w;
        acc[1][0] += a1 * bv.x; acc[1][1] += a1 * bv.y; acc[1][2] += a1 * bv.z; acc[1][3] += a1 * bv.w;
        acc[2][0] += a2v * bv.x; acc[2][1] += a2v * bv.y; acc[2][2] += a2v * bv.z; acc[2][3] += a2v * bv.w;
        acc[3][0] += a3 * bv.x; acc[3][1] += a3 * bv.y; acc[3][2] += a3 * bv.z; acc[3][3] += a3 * bv.w;
    }
    __syncthreads();
#pragma unroll
    for (int r = 0; r < 4; r++) {
        int t = r * 16 + (tid >> 4);
        int d4 = (tid & 15) * 4;
        float4 kv = *(const float4*)&g_k[(rowbase + t) * Dn + h * 64 + d4];
        sX[(d4 + 0) * 65 + t] = kv.x;
        sX[(d4 + 1) * 65 + t] = kv.y;
        sX[(d4 + 2) * 65 + t] = kv.z;
        sX[(d4 + 3) * 65 + t] = kv.w;
    }
    __syncthreads();

    float a2[4][4];
#pragma unroll
    for (int i = 0; i < 4; i++)
#pragma unroll
        for (int j = 0; j < 4; j++) a2[i][j] = 0.f;
#pragma unroll 8
    for (int d = 0; d < 64; d++) {
        float af[4], bf[4];
#pragma unroll
        for (int i = 0; i < 4; i++) af[i] = sqT[d * 65 + ty * 4 + i];
#pragma unroll
        for (int j = 0; j < 4; j++) bf[j] = sX[d * 65 + tx * 4 + j];
#pragma unroll
        for (int i = 0; i < 4; i++)
#pragma unroll
            for (int j = 0; j < 4; j++) a2[i][j] += af[i] * bf[j];
    }
#pragma unroll
    for (int j = 0; j < 4; j++) {
        int s = tx * 4 + j;
        float bscale = sbeta[s];
        float4 v4;
        v4.x = (s <= ty * 4 + 0) ? a2[0][j] * bscale : 0.f;
        v4.y = (s <= ty * 4 + 1) ? a2[1][j] * bscale : 0.f;
        v4.z = (s <= ty * 4 + 2) ? a2[2][j] * bscale : 0.f;
        v4.w = (s <= ty * 4 + 3) ? a2[3][j] * bscale : 0.f;
        *(float4*)&sA[s * 64 + ty * 4] = v4;
    }
    __syncthreads();
#pragma unroll
    for (int r = 0; r < 4; r++) {
        int t = r * 16 + (tid >> 4);
        int e4 = (tid & 15) * 4;
        *(float4*)&sX[t * 64 + e4] =
            *(const float4*)&g_v[(rowbase + t) * Dn + h * 64 + e4];
    }
    __syncthreads();

#pragma unroll 8
    for (int s = 0; s < 64; s++) {
        float4 av = *(const float4*)&sA[s * 64 + ty * 4];
        float4 bv = *(const float4*)&sX[s * 64 + tx * 4];
        const float af[4] = {av.x, av.y, av.z, av.w};
        const float bf[4] = {bv.x, bv.y, bv.z, bv.w};
#pragma unroll
        for (int i = 0; i < 4; i++)
#pragma unroll
            for (int j = 0; j < 4; j++) acc[i][j] += af[i] * bf[j];
    }
    // write attn as bf16 hi/lo for the tensor-core output GEMM
#pragma unroll
    for (int i = 0; i < 4; i++) {
        size_t base = (rowbase + ty * 4 + i) * Dn + h * 64 + tx * 4;
        __nv_bfloat16 hh[4], ll[4];
#pragma unroll
        for (int j = 0; j < 4; j++) split_hl(acc[i][j], hh[j], ll[j]);
        __nv_bfloat162 h01, h23, l01, l23;
        h01.x = hh[0]; h01.y = hh[1]; h23.x = hh[2]; h23.y = hh[3];
        l01.x = ll[0]; l01.y = ll[1]; l23.x = ll[2]; l23.y = ll[3];
        *(__nv_bfloat162*)(g_ah + base)     = h01;
        *(__nv_bfloat162*)(g_ah + base + 2) = h23;
        *(__nv_bfloat162*)(g_al + base)     = l01;
        *(__nv_bfloat162*)(g_al + base + 2) = l23;
    }
}

// ---------------------------------------------------------------------------
extern "C" void kernel_launch(void* const* d_in, const int* in_sizes, int n_in,
                              void* d_out, int out_size) {
    const float* x  = (const float*)d_in[0];
    const float* Wq = (const float*)d_in[1];
    const float* Wk = (const float*)d_in[2];
    const float* Wv = (const float*)d_in[3];
    const float* Wo = (const float*)d_in[4];
    const float* Wb = (const float*)d_in[5];
    const float* bb = (const float*)d_in[6];
    float* out = (float*)d_out;

    cudaFuncSetAttribute(mm_qkv_kernel,
                         cudaFuncAttributeMaxDynamicSharedMemorySize, MM_SMEM_B);
    cudaFuncSetAttribute(mm_out_kernel,
                         cudaFuncAttributeMaxDynamicSharedMemorySize, MM_SMEM_B);
    cudaFuncSetAttribute(chunk_out_kernel,
                         cudaFuncAttributeMaxDynamicSharedMemorySize, 12480 * 4);

    // operand conversion: x -> bf16 hi/lo, W -> W^T bf16 hi/lo
    convert_x_kernel<<<NT * Dn / 1024, 256>>>(x);
    convert_w_kernel<<<dim3(32, 32, 4), dim3(32, 8)>>>(Wq, Wk, Wv, Wo);
    // q,k,v projections on tensor cores (3-term bf16 hi/lo)
    mm_qkv_kernel<<<dim3(Dn / 128, NT / 128, 3), 256, MM_SMEM_B>>>();
    // gates
    beta_kernel<<<NT / 16, 256>>>(x, Wb, bb);
    // l2 normalize q,k
    l2norm_kernel<<<(2 * NT * Hn) / 8, 256>>>();
    // chunk-local state deltas
    chunk_delta_kernel<<<dim3(NCn, BHn), 256>>>();
    // exclusive prefix over chunk states
    prefix_kernel<<<BHn, 256>>>();
    // per-chunk outputs (writes attn bf16 hi/lo)
    chunk_out_kernel<<<dim3(NCn, BHn), 256, 12480 * 4>>>();
    // final projection on tensor cores
    mm_out_kernel<<<dim3(Dn / 128, NT / 128), 256, MM_SMEM_B>>>(out);
}

// round 8
// speedup vs baseline: 2.3592x; 1.0569x over previous
#include <cuda_runtime.h>
#include <cuda_bf16.h>
#include <math.h>
#include <stdint.h>

#define Bn 2
#define Ln 1024
#define Dn 1024
#define Hn 16
#define HDn 64
#define NT 2048       // Bn*Ln tokens
#define NCn 16        // chunks per sequence (Ln/64)
#define BHn 32        // Bn*Hn

// ---------------- scratch (static device globals; no allocation allowed) ---
__device__ float g_q[NT * Dn];
__device__ float g_k[NT * Dn];
__device__ float g_v[NT * Dn];
__device__ float g_beta[NT * Hn];
__device__ float g_sdelta[BHn * NCn * HDn * HDn];
__device__ float g_sprefix[BHn * NCn * HDn * HDn];
// bf16 hi/lo operands for tensor-core GEMMs
__device__ __nv_bfloat16 g_xh[NT * Dn], g_xl[NT * Dn];
__device__ __nv_bfloat16 g_wth[4 * Dn * Dn], g_wtl[4 * Dn * Dn];  // W^T [N][K], 4 mats
__device__ __nv_bfloat16 g_ah[NT * Dn], g_al[NT * Dn];            // attn hi/lo

// =================== helpers ===============================================
__device__ __forceinline__ uint32_t smem_u32(const void* p) {
    uint32_t a;
    asm("{ .reg .u64 t; cvta.to.shared.u64 t, %1; cvt.u32.u64 %0, t; }"
        : "=r"(a) : "l"(p));
    return a;
}
__device__ __forceinline__ void cp_async16(uint32_t saddr, const void* gptr) {
    asm volatile("cp.async.cg.shared.global [%0], [%1], 16;"
                 :: "r"(saddr), "l"(gptr) : "memory");
}
#define CP_COMMIT() asm volatile("cp.async.commit_group;" ::: "memory")
#define CP_WAIT0()  asm volatile("cp.async.wait_group 0;" ::: "memory")

__device__ __forceinline__ void ldsm_x4(uint32_t* r, uint32_t addr) {
    asm volatile("ldmatrix.sync.aligned.m8n8.x4.shared.b16 {%0,%1,%2,%3}, [%4];"
                 : "=r"(r[0]), "=r"(r[1]), "=r"(r[2]), "=r"(r[3]) : "r"(addr));
}
__device__ __forceinline__ void ldsm_x2(uint32_t* r, uint32_t addr) {
    asm volatile("ldmatrix.sync.aligned.m8n8.x2.shared.b16 {%0,%1}, [%2];"
                 : "=r"(r[0]), "=r"(r[1]) : "r"(addr));
}

// mma.sync m16n8k16 bf16 -> fp32 (HMMA path; plain compute_80+ PTX)
__device__ __forceinline__ void mma16816(float* c, const uint32_t* a, const uint32_t* b) {
    asm volatile(
        "mma.sync.aligned.m16n8k16.row.col.f32.bf16.bf16.f32 "
        "{%0,%1,%2,%3}, {%4,%5,%6,%7}, {%8,%9}, {%0,%1,%2,%3};"
        : "+f"(c[0]), "+f"(c[1]), "+f"(c[2]), "+f"(c[3])
        : "r"(a[0]), "r"(a[1]), "r"(a[2]), "r"(a[3]), "r"(b[0]), "r"(b[1]));
}

__device__ __forceinline__ void split_hl(float v, __nv_bfloat16& h, __nv_bfloat16& l) {
    h = __float2bfloat16(v);
    l = __float2bfloat16(v - __bfloat162float(h));
}

// ---------------- operand conversion kernels -------------------------------
__global__ void __launch_bounds__(256) convert_x_kernel(const float* __restrict__ x) {
    size_t i = ((size_t)blockIdx.x * 256 + threadIdx.x) * 4;
    float4 v = *(const float4*)(x + i);
    float f[4] = {v.x, v.y, v.z, v.w};
    __nv_bfloat16 h[4], l[4];
#pragma unroll
    for (int j = 0; j < 4; j++) split_hl(f[j], h[j], l[j]);
    __nv_bfloat162 h01, h23, l01, l23;
    h01.x = h[0]; h01.y = h[1]; h23.x = h[2]; h23.y = h[3];
    l01.x = l[0]; l01.y = l[1]; l23.x = l[2]; l23.y = l[3];
    *(__nv_bfloat162*)(g_xh + i)     = h01;
    *(__nv_bfloat162*)(g_xh + i + 2) = h23;
    *(__nv_bfloat162*)(g_xl + i)     = l01;
    *(__nv_bfloat162*)(g_xl + i + 2) = l23;
}

// transpose W[K][N] -> Wt[N][K], split hi/lo
__global__ void __launch_bounds__(256) convert_w_kernel(
    const float* __restrict__ Wq, const float* __restrict__ Wk,
    const float* __restrict__ Wv, const float* __restrict__ Wo) {
    __shared__ float t[32][33];
    const float* W = (blockIdx.z == 0) ? Wq : (blockIdx.z == 1) ? Wk
                   : (blockIdx.z == 2) ? Wv : Wo;
    int n0 = blockIdx.x * 32, k0 = blockIdx.y * 32;
    int tx = threadIdx.x, ty = threadIdx.y;  // block (32,8)
#pragma unroll
    for (int r = 0; r < 4; r++)
        t[ty + 8 * r][tx] = W[(size_t)(k0 + ty + 8 * r) * Dn + n0 + tx];
    __syncthreads();
    size_t ob = (size_t)blockIdx.z * Dn * Dn;
#pragma unroll
    for (int r = 0; r < 4; r++) {
        float v = t[tx][ty + 8 * r];
        size_t o = ob + (size_t)(n0 + ty + 8 * r) * Dn + k0 + tx;
        __nv_bfloat16 h, l;
        split_hl(v, h, l);
        g_wth[o] = h;
        g_wtl[o] = l;
    }
}

// ---------------- bf16 3-term MMA GEMM: C[2048x1024] = A @ Wt^T ------------
// 128x128 CTA tile, BK=32, 8 warps 2(M)x4(N), warp tile 64x32, ldmatrix frags.
#define KPAD 40                        // bf16 elems per smem row (32 + 8 pad)
#define TILE_E (128 * KPAD)            // elems per operand tile
#define STAGE_E (4 * TILE_E)           // Ah, Al, Bh, Bl
#define MM_SMEM_B (2 * STAGE_E * 2)    // 81920 bytes

__device__ __forceinline__ void mm_issue_stage(
    uint32_t sbase, int s, int kc, int tid,
    const __nv_bfloat16* Ah, const __nv_bfloat16* Al,
    const __nv_bfloat16* Bh, const __nv_bfloat16* Bl) {
    uint32_t st = sbase + (uint32_t)s * (STAGE_E * 2);
#pragma unroll
    for (int j = 0; j < 2; j++) {
        int idx = tid + j * 256;               // 0..511
        int row = idx >> 2, seg = idx & 3;
        size_t go = (size_t)row * Dn + kc * 32 + seg * 8;
        uint32_t so = (uint32_t)(row * KPAD + seg * 8) * 2;
        cp_async16(st + so,                    Ah + go);
        cp_async16(st + TILE_E * 2 + so,       Al + go);
        cp_async16(st + 2 * TILE_E * 2 + so,   Bh + go);
        cp_async16(st + 3 * TILE_E * 2 + so,   Bl + go);
    }
    CP_COMMIT();
}

__device__ __forceinline__ void mm_gemm_body(
    const __nv_bfloat16* __restrict__ Agh, const __nv_bfloat16* __restrict__ Agl,
    const __nv_bfloat16* __restrict__ Bgh, const __nv_bfloat16* __restrict__ Bgl,
    float* __restrict__ C) {
    extern __shared__ __nv_bfloat16 sm[];
    const uint32_t sbase = smem_u32(sm);
    const int tid = threadIdx.x, lane = tid & 31, wid = tid >> 5;
    const int wm = wid & 1, wn = wid >> 1;
    const int m0 = blockIdx.y * 128, n0 = blockIdx.x * 128;

    const __nv_bfloat16* Ah = Agh + (size_t)m0 * Dn;
    const __nv_bfloat16* Al = Agl + (size_t)m0 * Dn;
    const __nv_bfloat16* Bh = Bgh + (size_t)n0 * Dn;
    const __nv_bfloat16* Bl = Bgl + (size_t)n0 * Dn;

    float c[4][4][4];
#pragma unroll
    for (int i = 0; i < 4; i++)
#pragma unroll
        for (int j = 0; j < 4; j++)
#pragma unroll
            for (int r = 0; r < 4; r++) c[i][j][r] = 0.f;

    mm_issue_stage(sbase, 0, 0, tid, Ah, Al, Bh, Bl);

    // ldmatrix lane addressing (bf16 elements)
    const int a_r = (lane & 7) + ((lane >> 3) & 1) * 8;  // row in 16-row tile
    const int a_c = (lane >> 4) * 8;                     // k col-half 0/8
    const int b_r = lane & 7;                            // row in 8-row tile
    const int b_c = ((lane >> 3) & 1) * 8;               // k col-half (lanes 0-15)
    // epilogue addressing
    const int g4 = lane >> 2;
    const int cpair = (lane & 3) * 2;

    for (int kc = 0; kc < 32; kc++) {
        CP_WAIT0();
        __syncthreads();
        if (kc + 1 < 32)
            mm_issue_stage(sbase, (kc + 1) & 1, kc + 1, tid, Ah, Al, Bh, Bl);

        const uint32_t st = sbase + (uint32_t)(kc & 1) * (STAGE_E * 2);
        const uint32_t stAh = st;
        const uint32_t stAl = st + TILE_E * 2;
        const uint32_t stBh = st + 2 * TILE_E * 2;
        const uint32_t stBl = st + 3 * TILE_E * 2;

#pragma unroll
        for (int ks = 0; ks < 2; ks++) {
            const int kk = ks * 16;
            uint32_t bh[4][2], bl[4][2];
#pragma unroll
            for (int nf = 0; nf < 4; nf++) {
                uint32_t bo = (uint32_t)((wn * 32 + nf * 8 + b_r) * KPAD + kk + b_c) * 2;
                ldsm_x2(bh[nf], stBh + bo);
                ldsm_x2(bl[nf], stBl + bo);
            }
#pragma unroll
            for (int mf = 0; mf < 4; mf++) {
                uint32_t ao = (uint32_t)((wm * 64 + mf * 16 + a_r) * KPAD + kk + a_c) * 2;
                uint32_t ah[4], al[4];
                ldsm_x4(ah, stAh + ao);
                ldsm_x4(al, stAl + ao);
#pragma unroll
                for (int nf = 0; nf < 4; nf++) {
                    mma16816(c[mf][nf], ah, bh[nf]);
                    mma16816(c[mf][nf], ah, bl[nf]);
                    mma16816(c[mf][nf], al, bh[nf]);
                }
            }
        }
        __syncthreads();
    }

    // epilogue: write fp32 C
#pragma unroll
    for (int mf = 0; mf < 4; mf++) {
        int r = m0 + wm * 64 + mf * 16 + g4;
#pragma unroll
        for (int nf = 0; nf < 4; nf++) {
            int cc = n0 + wn * 32 + nf * 8 + cpair;
            *(float2*)(C + (size_t)r * Dn + cc)       = make_float2(c[mf][nf][0], c[mf][nf][1]);
            *(float2*)(C + (size_t)(r + 8) * Dn + cc) = make_float2(c[mf][nf][2], c[mf][nf][3]);
        }
    }
}

__global__ void __launch_bounds__(256, 2) mm_qkv_kernel() {
    const size_t wo = (size_t)blockIdx.z * Dn * Dn;
    float* C = (blockIdx.z == 0) ? g_q : (blockIdx.z == 1) ? g_k : g_v;
    mm_gemm_body(g_xh, g_xl, g_wth + wo, g_wtl + wo, C);
}
__global__ void __launch_bounds__(256, 2) mm_out_kernel(float* __restrict__ out) {
    mm_gemm_body(g_ah, g_al, g_wth + 3ull * Dn * Dn, g_wtl + 3ull * Dn * Dn, out);
}

// ---------------- beta = sigmoid(x @ Wb + bb) ------------------------------
// 16 tokens/block; double-buffered smem + 4 independent accumulators.
__global__ void __launch_bounds__(256) beta_kernel(const float* __restrict__ x,
                                                   const float* __restrict__ Wb,
                                                   const float* __restrict__ bbias) {
    __shared__ float sx[2][16 * 64];
    __shared__ float sW[2][64 * 16];
    const int tid = threadIdx.x;
    const int tx = tid & 15, ty = tid >> 4;
    const int row0 = blockIdx.x * 16;
    const int r = tid >> 4, c4 = (tid & 15) * 4;     // sx loader
    const int wr = tid >> 2, wc4 = (tid & 3) * 4;    // sW loader

    // preload chunk 0
    *(float4*)&sx[0][r * 64 + c4] = *(const float4*)&x[(size_t)(row0 + r) * Dn + c4];
    *(float4*)&sW[0][wr * 16 + wc4] = *(const float4*)&Wb[(size_t)wr * Hn + wc4];
    __syncthreads();

    float a0 = 0.f, a1 = 0.f, a2 = 0.f, a3 = 0.f;
    for (int c = 0; c < 16; c++) {
        const int cur = c & 1;
        float4 nx, nw;
        if (c < 15) {
            int k0 = (c + 1) * 64;
            nx = *(const float4*)&x[(size_t)(row0 + r) * Dn + k0 + c4];
            nw = *(const float4*)&Wb[(size_t)(k0 + wr) * Hn + wc4];
        }
#pragma unroll
        for (int kk = 0; kk < 64; kk += 4) {
            a0 += sx[cur][ty * 64 + kk + 0] * sW[cur][(kk + 0) * 16 + tx];
            a1 += sx[cur][ty * 64 + kk + 1] * sW[cur][(kk + 1) * 16 + tx];
            a2 += sx[cur][ty * 64 + kk + 2] * sW[cur][(kk + 2) * 16 + tx];
            a3 += sx[cur][ty * 64 + kk + 3] * sW[cur][(kk + 3) * 16 + tx];
        }
        if (c < 15) {
            *(float4*)&sx[cur ^ 1][r * 64 + c4] = nx;
            *(float4*)&sW[cur ^ 1][wr * 16 + wc4] = nw;
        }
        __syncthreads();
    }
    float acc = (a0 + a1) + (a2 + a3) + bbias[tx];
    g_beta[(size_t)(row0 + ty) * Hn + tx] = 1.f / (1.f + expf(-acc));
}

// ---------------- L2 normalize q,k per (b,l,h) over HD=64 ------------------
__global__ void __launch_bounds__(256) l2norm_kernel() {
    int gw = (blockIdx.x * 256 + threadIdx.x) >> 5;
    int lane = threadIdx.x & 31;
    float* ptr = (gw < NT * Hn) ? g_q : g_k;
    int row = (gw < NT * Hn) ? gw : gw - NT * Hn;
    size_t base = (size_t)(row >> 4) * Dn + (row & 15) * 64;
    float2 v = *(float2*)&ptr[base + lane * 2];
    float s = v.x * v.x + v.y * v.y;
#pragma unroll
    for (int o = 16; o > 0; o >>= 1) s += __shfl_xor_sync(0xffffffffu, s, o);
    float scale = 1.f / fmaxf(sqrtf(s), 1e-12f);
    v.x *= scale; v.y *= scale;
    *(float2*)&ptr[base + lane * 2] = v;
}

// ---------------- per-chunk state delta: dS = (beta*k)^T @ v ---------------
__global__ void __launch_bounds__(256) chunk_delta_kernel() {
    __shared__ float skb[64 * 64];
    __shared__ float sv[64 * 64];
    __shared__ float sbeta[64];
    const int c = blockIdx.x, bh = blockIdx.y;
    const int b = bh >> 4, h = bh & 15;
    const int tid = threadIdx.x;
    const int tx = tid & 15, ty = tid >> 4;
    const size_t rowbase = (size_t)b * Ln + c * 64;

    if (tid < 64) sbeta[tid] = g_beta[(rowbase + tid) * Hn + h];
    __syncthreads();
#pragma unroll
    for (int r = 0; r < 4; r++) {
        int t = r * 16 + (tid >> 4);
        int e4 = (tid & 15) * 4;
        size_t g = (rowbase + t) * Dn + h * 64 + e4;
        float4 kv = *(const float4*)&g_k[g];
        float bt = sbeta[t];
        kv.x *= bt; kv.y *= bt; kv.z *= bt; kv.w *= bt;
        *(float4*)&skb[t * 64 + e4] = kv;
        *(float4*)&sv[t * 64 + e4] = *(const float4*)&g_v[g];
    }
    __syncthreads();

    float acc[4][4];
#pragma unroll
    for (int i = 0; i < 4; i++)
#pragma unroll
        for (int j = 0; j < 4; j++) acc[i][j] = 0.f;
#pragma unroll 8
    for (int t = 0; t < 64; t++) {
        float4 a = *(const float4*)&skb[t * 64 + ty * 4];
        float4 b4 = *(const float4*)&sv[t * 64 + tx * 4];
        const float af[4] = {a.x, a.y, a.z, a.w};
        const float bf[4] = {b4.x, b4.y, b4.z, b4.w};
#pragma unroll
        for (int i = 0; i < 4; i++)
#pragma unroll
            for (int j = 0; j < 4; j++) acc[i][j] += af[i] * bf[j];
    }
    const size_t sbase = ((size_t)bh * NCn + c) * 4096;
#pragma unroll
    for (int i = 0; i < 4; i++)
        *(float4*)&g_sdelta[sbase + (ty * 4 + i) * 64 + tx * 4] =
            make_float4(acc[i][0], acc[i][1], acc[i][2], acc[i][3]);
}

// ---------------- exclusive prefix over 16 chunk states per (b,h) ----------
// grid (BHn, 4): blockIdx.y selects a 1024-element quarter of the 64x64 state
__global__ void __launch_bounds__(256) prefix_kernel() {
    const int bh = blockIdx.x;
    const int off = blockIdx.y * 1024 + threadIdx.x * 4;
    float4 acc = make_float4(0.f, 0.f, 0.f, 0.f);
    for (int c = 0; c < NCn; c++) {
        size_t base = ((size_t)bh * NCn + c) * 4096 + off;
        *(float4*)&g_sprefix[base] = acc;
        float4 d = *(const float4*)&g_sdelta[base];
        acc.x += d.x; acc.y += d.y; acc.z += d.z; acc.w += d.w;
    }
}

// ---------------- per-chunk output ----------------------------------------
// out = q @ S_prev + tril(q k^T) * beta @ v ; writes attn as bf16 hi/lo
__global__ void __launch_bounds__(256) chunk_out_kernel() {
    extern __shared__ float smf[];
    float* sqT = smf;             // [64][65] transposed q
    float* sX  = smf + 4160;      // multi-use
    float* sA  = smf + 8320;      // [64][64] A^T
    float* sbeta = smf + 12416;   // [64]
    const int c = blockIdx.x, bh = blockIdx.y;
    const int b = bh >> 4, h = bh & 15;
    const int tid = threadIdx.x;
    const int tx = tid & 15, ty = tid >> 4;
    const size_t rowbase = (size_t)b * Ln + c * 64;
    const size_t sbase = ((size_t)bh * NCn + c) * 4096;

    if (tid < 64) sbeta[tid] = g_beta[(rowbase + tid) * Hn + h];
#pragma unroll
    for (int r = 0; r < 4; r++) {
        int t = r * 16 + (tid >> 4);
        int d4 = (tid & 15) * 4;
        float4 qv = *(const float4*)&g_q[(rowbase + t) * Dn + h * 64 + d4];
        sqT[(d4 + 0) * 65 + t] = qv.x;
        sqT[(d4 + 1) * 65 + t] = qv.y;
        sqT[(d4 + 2) * 65 + t] = qv.z;
        sqT[(d4 + 3) * 65 + t] = qv.w;
    }
#pragma unroll
    for (int r = 0; r < 4; r++) {
        int idx = r * 1024 + tid * 4;
        *(float4*)&sX[idx] = *(const float4*)&g_sprefix[sbase + idx];
    }
    __syncthreads();

    float acc[4][4];
#pragma unroll
    for (int i = 0; i < 4; i++)
#pragma unroll
        for (int j = 0; j < 4; j++) acc[i][j] = 0.f;

#pragma unroll 8
    for (int d = 0; d < 64; d++) {
        float a0 = sqT[d * 65 + ty * 4 + 0];
        float a1 = sqT[d * 65 + ty * 4 + 1];
        float a2v = sqT[d * 65 + ty * 4 + 2];
        float a3 = sqT[d * 65 + ty * 4 + 3];
        float4 bv = *(const float4*)&sX[d * 64 + tx * 4];
        acc[0][0] += a0 * bv.x; acc[0][1] += a0 * bv.y; acc[0][2] += a0 * bv.z; acc[0][3] += a0 * bv.w;
        acc[1][0] += a1 * bv.x; acc[1][1] += a1 * bv.y; acc[1][2] += a1 * bv.z; acc[1][3] += a1 * bv.w;
        acc[2][0] += a2v * bv.x; acc[2][1] += a2v * bv.y; acc[2][2] += a2v * bv.z; acc[2][3] += a2v * bv.w;
        acc[3][0] += a3 * bv.x; acc[3][1] += a3 * bv.y; acc[3][2] += a3 * bv.z; acc[3][3] += a3 * bv.w;
    }
    __syncthreads();
#pragma unroll
    for (int r = 0; r < 4; r++) {
        int t = r * 16 + (tid >> 4);
        int d4 = (tid & 15) * 4;
        float4 kv = *(const float4*)&g_k[(rowbase + t) * Dn + h * 64 + d4];
        sX[(d4 + 0) * 65 + t] = kv.x;
        sX[(d4 + 1) * 65 + t] = kv.y;
        sX[(d4 + 2) * 65 + t] = kv.z;
        sX[(d4 + 3) * 65 + t] = kv.w;
    }
    __syncthreads();

    float a2[4][4];
#pragma unroll
    for (int i = 0; i < 4; i++)
#pragma unroll
        for (int j = 0; j < 4; j++) a2[i][j] = 0.f;
#pragma unroll 8
    for (int d = 0; d < 64; d++) {
        float af[4], bf[4];
#pragma unroll
        for (int i = 0; i < 4; i++) af[i] = sqT[d * 65 + ty * 4 + i];
#pragma unroll
        for (int j = 0; j < 4; j++) bf[j] = sX[d * 65 + tx * 4 + j];
#pragma unroll
        for (int i = 0; i < 4; i++)
#pragma unroll
            for (int j = 0; j < 4; j++) a2[i][j] += af[i] * bf[j];
    }
#pragma unroll
    for (int j = 0; j < 4; j++) {
        int s = tx * 4 + j;
        float bscale = sbeta[s];
        float4 v4;
        v4.x = (s <= ty * 4 + 0) ? a2[0][j] * bscale : 0.f;
        v4.y = (s <= ty * 4 + 1) ? a2[1][j] * bscale : 0.f;
        v4.z = (s <= ty * 4 + 2) ? a2[2][j] * bscale : 0.f;
        v4.w = (s <= ty * 4 + 3) ? a2[3][j] * bscale : 0.f;
        *(float4*)&sA[s * 64 + ty * 4] = v4;
    }
    __syncthreads();
#pragma unroll
    for (int r = 0; r < 4; r++) {
        int t = r * 16 + (tid >> 4);
        int e4 = (tid & 15) * 4;
        *(float4*)&sX[t * 64 + e4] =
            *(const float4*)&g_v[(rowbase + t) * Dn + h * 64 + e4];
    }
    __syncthreads();

#pragma unroll 8
    for (int s = 0; s < 64; s++) {
        float4 av = *(const float4*)&sA[s * 64 + ty * 4];
        float4 bv = *(const float4*)&sX[s * 64 + tx * 4];
        const float af[4] = {av.x, av.y, av.z, av.w};
        const float bf[4] = {bv.x, bv.y, bv.z, bv.w};
#pragma unroll
        for (int i = 0; i < 4; i++)
#pragma unroll
            for (int j = 0; j < 4; j++) acc[i][j] += af[i] * bf[j];
    }
    // write attn as bf16 hi/lo for the tensor-core output GEMM
#pragma unroll
    for (int i = 0; i < 4; i++) {
        size_t base = (rowbase + ty * 4 + i) * Dn + h * 64 + tx * 4;
        __nv_bfloat16 hh[4], ll[4];
#pragma unroll
        for (int j = 0; j < 4; j++) split_hl(acc[i][j], hh[j], ll[j]);
        __nv_bfloat162 h01, h23, l01, l23;
        h01.x = hh[0]; h01.y = hh[1]; h23.x = hh[2]; h23.y = hh[3];
        l01.x = ll[0]; l01.y = ll[1]; l23.x = ll[2]; l23.y = ll[3];
        *(__nv_bfloat162*)(g_ah + base)     = h01;
        *(__nv_bfloat162*)(g_ah + base + 2) = h23;
        *(__nv_bfloat162*)(g_al + base)     = l01;
        *(__nv_bfloat162*)(g_al + base + 2) = l23;
    }
}

// ---------------------------------------------------------------------------
extern "C" void kernel_launch(void* const* d_in, const int* in_sizes, int n_in,
                              void* d_out, int out_size) {
    const float* x  = (const float*)d_in[0];
    const float* Wq = (const float*)d_in[1];
    const float* Wk = (const float*)d_in[2];
    const float* Wv = (const float*)d_in[3];
    const float* Wo = (const float*)d_in[4];
    const float* Wb = (const float*)d_in[5];
    const float* bb = (const float*)d_in[6];
    float* out = (float*)d_out;

    cudaFuncSetAttribute(mm_qkv_kernel,
                         cudaFuncAttributeMaxDynamicSharedMemorySize, MM_SMEM_B);
    cudaFuncSetAttribute(mm_out_kernel,
                         cudaFuncAttributeMaxDynamicSharedMemorySize, MM_SMEM_B);
    cudaFuncSetAttribute(chunk_out_kernel,
                         cudaFuncAttributeMaxDynamicSharedMemorySize, 12480 * 4);

    // operand conversion: x -> bf16 hi/lo, W -> W^T bf16 hi/lo
    convert_x_kernel<<<NT * Dn / 1024, 256>>>(x);
    convert_w_kernel<<<dim3(32, 32, 4), dim3(32, 8)>>>(Wq, Wk, Wv, Wo);
    // q,k,v projections on tensor cores (3-term bf16 hi/lo)
    mm_qkv_kernel<<<dim3(Dn / 128, NT / 128, 3), 256, MM_SMEM_B>>>();
    // gates
    beta_kernel<<<NT / 16, 256>>>(x, Wb, bb);
    // l2 normalize q,k
    l2norm_kernel<<<(2 * NT * Hn) / 8, 256>>>();
    // chunk-local state deltas
    chunk_delta_kernel<<<dim3(NCn, BHn), 256>>>();
    // exclusive prefix over chunk states
    prefix_kernel<<<dim3(BHn, 4), 256>>>();
    // per-chunk outputs (writes attn bf16 hi/lo)
    chunk_out_kernel<<<dim3(NCn, BHn), 256, 12480 * 4>>>();
    // final projection on tensor cores
    mm_out_kernel<<<dim3(Dn / 128, NT / 128), 256, MM_SMEM_B>>>(out);
}